// round 3
// baseline (speedup 1.0000x reference)
#include <cuda_runtime.h>
#include <cstdint>

// VolumeRenderer: per-ray exclusive-cumprod transmittance * alpha, dot with rgb.
// alpha: [R, 128, 1] f32, rgbs: [R, 128, 3] f32 -> out [R, 3] f32.
//
// Persistent grid-stride kernel, one ray per warp per iteration, with a
// 2-stage software pipeline: next iteration's loads are issued BEFORE the
// current iteration's scan/reduce, keeping DRAM requests continuously in
// flight across the dependent shfl chains.

#define EPS 1e-10f

__global__ __launch_bounds__(256) void volume_render_pipe(
    const float* __restrict__ alpha,
    const float* __restrict__ rgbs,
    float* __restrict__ out,
    int R)
{
    const int lane = threadIdx.x & 31;
    const int gwarp = (blockIdx.x * blockDim.x + threadIdx.x) >> 5;
    const int nwarps = (gridDim.x * blockDim.x) >> 5;

    int ray = gwarp;
    if (ray >= R) return;

    // ---- prologue: load iteration 0 ----
    float4 a  = *(reinterpret_cast<const float4*>(alpha + (size_t)ray * 128) + lane);
    const float4* rg = reinterpret_cast<const float4*>(rgbs + (size_t)ray * 384) + lane * 3;
    float4 r0 = rg[0];
    float4 r1 = rg[1];
    float4 r2 = rg[2];

    while (true) {
        const int next = ray + nwarps;
        const bool hasNext = (next < R);

        // ---- issue NEXT iteration's loads first (kept live across compute) ----
        float4 an = make_float4(0.f, 0.f, 0.f, 0.f);
        float4 rn0 = an, rn1 = an, rn2 = an;
        if (hasNext) {
            an = *(reinterpret_cast<const float4*>(alpha + (size_t)next * 128) + lane);
            const float4* rgn = reinterpret_cast<const float4*>(rgbs + (size_t)next * 384) + lane * 3;
            rn0 = rgn[0];
            rn1 = rgn[1];
            rn2 = rgn[2];
        }

        // ---- compute current ray ----
        const float t0 = 1.0f - a.x + EPS;
        const float t1 = 1.0f - a.y + EPS;
        const float t2 = 1.0f - a.z + EPS;
        const float t3 = 1.0f - a.w + EPS;

        // inclusive warp scan (product) of per-lane 4-factor products
        float incl = (t0 * t1) * (t2 * t3);
        #pragma unroll
        for (int off = 1; off < 32; off <<= 1) {
            const float v = __shfl_up_sync(0xffffffffu, incl, off);
            if (lane >= off) incl *= v;
        }
        float excl = __shfl_up_sync(0xffffffffu, incl, 1);
        if (lane == 0) excl = 1.0f;

        // weighted accumulation over this lane's 4 samples
        float acc0 = 0.f, acc1 = 0.f, acc2 = 0.f;
        {
            float tr = excl, w;
            w = tr * a.x; acc0 = fmaf(w, r0.x, acc0); acc1 = fmaf(w, r0.y, acc1); acc2 = fmaf(w, r0.z, acc2); tr *= t0;
            w = tr * a.y; acc0 = fmaf(w, r0.w, acc0); acc1 = fmaf(w, r1.x, acc1); acc2 = fmaf(w, r1.y, acc2); tr *= t1;
            w = tr * a.z; acc0 = fmaf(w, r1.z, acc0); acc1 = fmaf(w, r1.w, acc1); acc2 = fmaf(w, r2.x, acc2); tr *= t2;
            w = tr * a.w; acc0 = fmaf(w, r2.y, acc0); acc1 = fmaf(w, r2.z, acc1); acc2 = fmaf(w, r2.w, acc2);
        }

        // butterfly reduce 3 channels across the warp
        #pragma unroll
        for (int off = 16; off > 0; off >>= 1) {
            acc0 += __shfl_xor_sync(0xffffffffu, acc0, off);
            acc1 += __shfl_xor_sync(0xffffffffu, acc1, off);
            acc2 += __shfl_xor_sync(0xffffffffu, acc2, off);
        }

        if (lane < 3) {
            const float v = (lane == 0) ? acc0 : ((lane == 1) ? acc1 : acc2);
            out[(size_t)ray * 3 + lane] = v;
        }

        if (!hasNext) break;

        // rotate pipeline
        a = an; r0 = rn0; r1 = rn1; r2 = rn2;
        ray = next;
    }
}

extern "C" void kernel_launch(void* const* d_in, const int* in_sizes, int n_in,
                              void* d_out, int out_size)
{
    const float* alpha = (const float*)d_in[0];   // [R,128,1]
    const float* rgbs  = (const float*)d_in[1];   // [R,128,3]
    float* out = (float*)d_out;                   // [R,3]

    const int R = in_sizes[0] / 128;

    const int threads = 256;          // 8 warps/block
    const int blocks = 152 * 6;       // persistent-ish: ~6 CTAs/SM on 152 SMs

    volume_render_pipe<<<blocks, threads>>>(alpha, rgbs, out, R);
}